// round 1
// baseline (speedup 1.0000x reference)
#include <cuda_runtime.h>
#include <cuda_bf16.h>

#define N_NODES 50000
#define N_EDGES 800000
#define VOCABSZ 4096
#define EMB_DIM 128
#define H2 256      // 2*HIDDEN
#define HID 128
#define N_POS 1024

// ---------------- scratch (device globals; no allocations allowed) ----------
__device__ float d_EW[VOCABSZ * H2];        // emb @ W1, 4 MB
__device__ float d_h1acc[N_NODES * H2];     // layer-1 pre-activation accumulator (51 MB)
__device__ float d_dinv[N_NODES];
__device__ int   d_deg[N_NODES];
__device__ int   d_cnt[N_NODES];            // multiplicity of node in x_position
__device__ unsigned char d_need[N_NODES];   // h1 needed at this node?
__device__ float d_svec[H2];                // layer-2 weighted sum of h1 rows
__device__ float d_zbar[HID];

__device__ __forceinline__ void red4(float4* p, float a, float b, float c, float d) {
    asm volatile("red.global.add.v4.f32 [%0], {%1,%2,%3,%4};"
                 :: "l"(p), "f"(a), "f"(b), "f"(c), "f"(d) : "memory");
}

// ---------------- K1: EW = emb @ W1  (4096x128 @ 128x256) -------------------
__global__ void k_ew(const float* __restrict__ emb, const float* __restrict__ W1) {
    __shared__ float se[16 * 128];
    int t0 = blockIdx.x * 16;
    for (int i = threadIdx.x; i < 16 * 128; i += 256) se[i] = emb[t0 * 128 + i];
    __syncthreads();
    int j = threadIdx.x;  // output column 0..255
    float acc[16];
#pragma unroll
    for (int r = 0; r < 16; r++) acc[r] = 0.f;
    for (int k = 0; k < 128; k++) {
        float w = W1[k * H2 + j];
#pragma unroll
        for (int r = 0; r < 16; r++) acc[r] += se[r * 128 + k] * w;
    }
#pragma unroll
    for (int r = 0; r < 16; r++) d_EW[(t0 + r) * H2 + j] = acc[r];
}

// ---------------- K2: degree + selected-count -------------------------------
__global__ void k_deg(const int* __restrict__ col, const int* __restrict__ pos) {
    int i = blockIdx.x * blockDim.x + threadIdx.x;
    if (i < N_EDGES) atomicAdd(&d_deg[col[i]], 1);
    if (i < N_POS)   atomicAdd(&d_cnt[pos[i]], 1);
}

// ---------------- K3: dinv + need flags from selection ----------------------
__global__ void k_dinv() {
    int v = blockIdx.x * blockDim.x + threadIdx.x;
    if (v < N_NODES) {
        d_dinv[v] = rsqrtf((float)d_deg[v] + 1.0f);  // +1 self loop; always > 0
        d_need[v] = (d_cnt[v] > 0) ? 1 : 0;
    }
}

// ---------------- K4: mark sources of edges into selected nodes -------------
__global__ void k_flag(const int* __restrict__ row, const int* __restrict__ col) {
    int i = blockIdx.x * blockDim.x + threadIdx.x;
    if (i < N_EDGES && d_cnt[col[i]] > 0) d_need[row[i]] = 1;
}

// ---------------- K5: init h1acc rows with layer-1 self-loop term -----------
__global__ void k_self1(const int* __restrict__ x) {
    int u = blockIdx.x;
    if (!d_need[u]) return;
    float d2 = d_dinv[u] * d_dinv[u];
    const float4* src = (const float4*)(d_EW + x[u] * H2);
    float4* dst = (float4*)(d_h1acc + u * H2);
    float4 v = src[threadIdx.x];
    dst[threadIdx.x] = make_float4(v.x * d2, v.y * d2, v.z * d2, v.w * d2);
}

// ---------------- K6: layer-1 pruned edge scatter (the heavy kernel) --------
__global__ void k_scatter1(const int* __restrict__ row, const int* __restrict__ col,
                           const int* __restrict__ x) {
    int lane = threadIdx.x & 31;
    int gw = (blockIdx.x * blockDim.x + threadIdx.x) >> 5;
    int nw = (gridDim.x * blockDim.x) >> 5;
    for (int base = gw * 32; base < N_EDGES; base += nw * 32) {
        int e = base + lane;
        int r = 0, c = 0; bool ok = false;
        if (e < N_EDGES) { r = row[e]; c = col[e]; ok = (d_need[c] != 0); }
        unsigned m = __ballot_sync(0xffffffffu, ok);
        while (m) {
            int s = __ffs(m) - 1; m &= m - 1;
            int rr = __shfl_sync(0xffffffffu, r, s);
            int cc = __shfl_sync(0xffffffffu, c, s);
            float w = d_dinv[rr] * d_dinv[cc];
            const float4* sp = (const float4*)(d_EW + x[rr] * H2);
            float4* dp = (float4*)(d_h1acc + cc * H2);
            float4 v0 = sp[lane];
            float4 v1 = sp[lane + 32];
            red4(dp + lane,      w * v0.x, w * v0.y, w * v0.z, w * v0.w);
            red4(dp + lane + 32, w * v1.x, w * v1.y, w * v1.z, w * v1.w);
        }
    }
}

// ---------------- K7: layer-2 edge accumulation into svec -------------------
__global__ void k_layer2(const int* __restrict__ row, const int* __restrict__ col,
                         const float* __restrict__ b1) {
    __shared__ float sacc[H2];
    if (threadIdx.x < H2) sacc[threadIdx.x] = 0.f;
    __syncthreads();
    int lane = threadIdx.x & 31;
    int gw = (blockIdx.x * blockDim.x + threadIdx.x) >> 5;
    int nw = (gridDim.x * blockDim.x) >> 5;
    float4 a0 = make_float4(0, 0, 0, 0), a1 = make_float4(0, 0, 0, 0);
    float4 bb0 = ((const float4*)b1)[lane];
    float4 bb1 = ((const float4*)b1)[lane + 32];
    for (int base = gw * 32; base < N_EDGES; base += nw * 32) {
        int e = base + lane;
        int r = 0, c = 0, k = 0;
        if (e < N_EDGES) { r = row[e]; c = col[e]; k = d_cnt[c]; }
        unsigned m = __ballot_sync(0xffffffffu, k > 0);
        while (m) {
            int s = __ffs(m) - 1; m &= m - 1;
            int rr = __shfl_sync(0xffffffffu, r, s);
            int cc = __shfl_sync(0xffffffffu, c, s);
            int kk = __shfl_sync(0xffffffffu, k, s);
            float w = d_dinv[rr] * d_dinv[cc] * (float)kk;
            const float4* hp = (const float4*)(d_h1acc + rr * H2);
            float4 h0 = hp[lane], h1 = hp[lane + 32];
            a0.x += w * fmaxf(h0.x + bb0.x, 0.f);
            a0.y += w * fmaxf(h0.y + bb0.y, 0.f);
            a0.z += w * fmaxf(h0.z + bb0.z, 0.f);
            a0.w += w * fmaxf(h0.w + bb0.w, 0.f);
            a1.x += w * fmaxf(h1.x + bb1.x, 0.f);
            a1.y += w * fmaxf(h1.y + bb1.y, 0.f);
            a1.z += w * fmaxf(h1.z + bb1.z, 0.f);
            a1.w += w * fmaxf(h1.w + bb1.w, 0.f);
        }
    }
    // combine 8 warps -> smem, then one vector red per 4 floats
    atomicAdd(&sacc[4 * lane + 0], a0.x);
    atomicAdd(&sacc[4 * lane + 1], a0.y);
    atomicAdd(&sacc[4 * lane + 2], a0.z);
    atomicAdd(&sacc[4 * lane + 3], a0.w);
    atomicAdd(&sacc[128 + 4 * lane + 0], a1.x);
    atomicAdd(&sacc[128 + 4 * lane + 1], a1.y);
    atomicAdd(&sacc[128 + 4 * lane + 2], a1.z);
    atomicAdd(&sacc[128 + 4 * lane + 3], a1.w);
    __syncthreads();
    if (threadIdx.x < 64) {
        float4* sv = (float4*)d_svec;
        float4 p = ((float4*)sacc)[threadIdx.x];
        red4(sv + threadIdx.x, p.x, p.y, p.z, p.w);
    }
}

// ---------------- K8: layer-2 self-loop terms over x_position ---------------
__global__ void k_self2(const int* __restrict__ pos, const float* __restrict__ b1) {
    int j = threadIdx.x;  // 256
    float acc = 0.f;
    int p0 = blockIdx.x * 32;
    float bj = b1[j];
    for (int p = p0; p < p0 + 32; p++) {
        int v = pos[p];
        float d2 = d_dinv[v] * d_dinv[v];
        acc += d2 * fmaxf(d_h1acc[v * H2 + j] + bj, 0.f);
    }
    atomicAdd(&d_svec[j], acc);
}

// ---------------- K9a: zbar = (svec/1024) @ W2 + b2 -------------------------
__global__ void k_zbar(const float* __restrict__ W2, const float* __restrict__ b2) {
    int j = threadIdx.x;  // 128
    float acc = 0.f;
    for (int k = 0; k < H2; k++) acc += d_svec[k] * W2[k * HID + j];
    d_zbar[j] = acc * (1.0f / (float)N_POS) + b2[j];
}

// ---------------- K9b: out = zbar @ Wc + bc ---------------------------------
__global__ void k_out(const float* __restrict__ Wc, const float* __restrict__ bc,
                      float* __restrict__ out) {
    __shared__ float zb[HID];
    if (threadIdx.x < HID) zb[threadIdx.x] = d_zbar[threadIdx.x];
    __syncthreads();
    int c = blockIdx.x * 256 + threadIdx.x;
    float acc = bc[c];
#pragma unroll 8
    for (int j = 0; j < HID; j++) acc += zb[j] * Wc[j * VOCABSZ + c];
    out[c] = acc;
}

extern "C" void kernel_launch(void* const* d_in, const int* in_sizes, int n_in,
                              void* d_out, int out_size) {
    const int*   x    = (const int*)d_in[0];
    const int*   ei   = (const int*)d_in[1];
    const int*   pos  = (const int*)d_in[2];
    const float* emb  = (const float*)d_in[3];
    const float* W1   = (const float*)d_in[4];
    const float* b1   = (const float*)d_in[5];
    const float* W2   = (const float*)d_in[6];
    const float* b2   = (const float*)d_in[7];
    const float* Wc   = (const float*)d_in[8];
    const float* bc   = (const float*)d_in[9];
    float* out = (float*)d_out;
    const int* row = ei;
    const int* col = ei + N_EDGES;

    void *pdeg, *pcnt, *pneed, *psvec;
    cudaGetSymbolAddress(&pdeg, d_deg);
    cudaGetSymbolAddress(&pcnt, d_cnt);
    cudaGetSymbolAddress(&pneed, d_need);
    cudaGetSymbolAddress(&psvec, d_svec);
    cudaMemsetAsync(pdeg, 0, N_NODES * sizeof(int), 0);
    cudaMemsetAsync(pcnt, 0, N_NODES * sizeof(int), 0);
    cudaMemsetAsync(pneed, 0, N_NODES, 0);
    cudaMemsetAsync(psvec, 0, H2 * sizeof(float), 0);

    k_ew<<<VOCABSZ / 16, 256>>>(emb, W1);
    k_deg<<<(N_EDGES + 255) / 256, 256>>>(col, pos);
    k_dinv<<<(N_NODES + 255) / 256, 256>>>();
    k_flag<<<(N_EDGES + 255) / 256, 256>>>(row, col);
    k_self1<<<N_NODES, 64>>>(x);
    k_scatter1<<<N_EDGES / 256, 256>>>(row, col, x);   // 3125 blocks = 25000 warps, 1 chunk each
    k_layer2<<<1024, 256>>>(row, col, b1);
    k_self2<<<N_POS / 32, 256>>>(pos, b1);
    k_zbar<<<1, 128>>>(W2, b2);
    k_out<<<VOCABSZ / 256, 256>>>(Wc, bc, out);
}

// round 2
// speedup vs baseline: 1.5116x; 1.5116x over previous
#include <cuda_runtime.h>
#include <cuda_bf16.h>

#define N_NODES 50000
#define N_EDGES 800000
#define VOCABSZ 4096
#define EMB_DIM 128
#define H2 256      // 2*HIDDEN
#define HID 128
#define N_POS 1024
#define NSCAN_BLK 196   // ceil(50000/256)

// ---------------- scratch (device globals) ----------------------------------
__device__ float d_EW[VOCABSZ * H2];        // emb @ W1, 4 MB (L2-resident)
__device__ float d_dinv[N_NODES];
__device__ int   d_deg[N_NODES];            // raw in-degree (no self loop)
__device__ int   d_cnt[N_NODES];            // multiplicity in x_position
__device__ float d_coef[N_NODES];           // layer-2 weight per needed node
__device__ unsigned char d_need[N_NODES];   // h1 needed at this node?
__device__ int   d_start[N_NODES];          // CSR start
__device__ int   d_cursor[N_NODES];         // CSR fill cursor
__device__ int   d_startloc[N_NODES];       // block-local exclusive scan
__device__ int   d_blksum[256];
__device__ int   d_blkoff[256];
__device__ int   d_list[N_NODES];           // compact list of needed nodes
__device__ int   d_nneed;
__device__ int2  d_csr[N_EDGES];            // {x[row], dinv[row]*dinv[col]} per kept edge
__device__ float d_svec[H2];
__device__ float d_zbar[HID];

__device__ __forceinline__ void red4(float4* p, float a, float b, float c, float d) {
    asm volatile("red.global.add.v4.f32 [%0], {%1,%2,%3,%4};"
                 :: "l"(p), "f"(a), "f"(b), "f"(c), "f"(d) : "memory");
}

// ---------------- K1: EW = emb @ W1 -----------------------------------------
__global__ void k_ew(const float* __restrict__ emb, const float* __restrict__ W1) {
    __shared__ float se[16 * 128];
    int t0 = blockIdx.x * 16;
    for (int i = threadIdx.x; i < 16 * 128; i += 256) se[i] = emb[t0 * 128 + i];
    __syncthreads();
    int j = threadIdx.x;
    float acc[16];
#pragma unroll
    for (int r = 0; r < 16; r++) acc[r] = 0.f;
    for (int k = 0; k < 128; k++) {
        float w = W1[k * H2 + j];
#pragma unroll
        for (int r = 0; r < 16; r++) acc[r] += se[r * 128 + k] * w;
    }
#pragma unroll
    for (int r = 0; r < 16; r++) d_EW[(t0 + r) * H2 + j] = acc[r];
}

// ---------------- K2: degree + selected-count (int4 vectorized) -------------
__global__ void k_deg(const int* __restrict__ col, const int* __restrict__ pos) {
    int i4 = blockIdx.x * blockDim.x + threadIdx.x;
    if (i4 < N_EDGES / 4) {
        int4 c = ((const int4*)col)[i4];
        atomicAdd(&d_deg[c.x], 1);
        atomicAdd(&d_deg[c.y], 1);
        atomicAdd(&d_deg[c.z], 1);
        atomicAdd(&d_deg[c.w], 1);
    }
    if (i4 < N_POS) atomicAdd(&d_cnt[pos[i4]], 1);
}

// ---------------- K3: dinv + need flags from positions ----------------------
__global__ void k_dinv(const int* __restrict__ pos) {
    int v = blockIdx.x * blockDim.x + threadIdx.x;
    if (v < N_NODES) d_dinv[v] = rsqrtf((float)d_deg[v] + 1.0f);
    if (v < N_POS) d_need[pos[v]] = 1;
}

// ---------------- K4: per-source coef + need flags (int4) -------------------
__global__ void k_coef(const int* __restrict__ row, const int* __restrict__ col) {
    int i4 = blockIdx.x * blockDim.x + threadIdx.x;
    if (i4 >= N_EDGES / 4) return;
    int4 c = ((const int4*)col)[i4];
    int4 r = ((const int4*)row)[i4];
    int k;
#define DO_E(rr, cc) \
    k = d_cnt[cc]; \
    if (k > 0) { \
        atomicAdd(&d_coef[rr], d_dinv[rr] * d_dinv[cc] * (float)k); \
        d_need[rr] = 1; \
    }
    DO_E(r.x, c.x) DO_E(r.y, c.y) DO_E(r.z, c.z) DO_E(r.w, c.w)
#undef DO_E
}

// ---------------- K5a/b/c: exclusive scan of needed-node sizes --------------
__global__ void k_scan1() {
    __shared__ int s[256];
    int u = blockIdx.x * 256 + threadIdx.x;
    int sz = (u < N_NODES && d_need[u]) ? d_deg[u] : 0;
    s[threadIdx.x] = sz;
    __syncthreads();
#pragma unroll
    for (int off = 1; off < 256; off <<= 1) {
        int v = (threadIdx.x >= off) ? s[threadIdx.x - off] : 0;
        __syncthreads();
        s[threadIdx.x] += v;
        __syncthreads();
    }
    if (u < N_NODES) d_startloc[u] = s[threadIdx.x] - sz;
    if (threadIdx.x == 255) d_blksum[blockIdx.x] = s[255];
}
__global__ void k_scan2() {
    __shared__ int s[256];
    int sz = (threadIdx.x < NSCAN_BLK) ? d_blksum[threadIdx.x] : 0;
    s[threadIdx.x] = sz;
    __syncthreads();
#pragma unroll
    for (int off = 1; off < 256; off <<= 1) {
        int v = (threadIdx.x >= off) ? s[threadIdx.x - off] : 0;
        __syncthreads();
        s[threadIdx.x] += v;
        __syncthreads();
    }
    d_blkoff[threadIdx.x] = s[threadIdx.x] - sz;
}
__global__ void k_scan3() {
    int u = blockIdx.x * 256 + threadIdx.x;
    if (u >= N_NODES) return;
    int st = d_startloc[u] + d_blkoff[blockIdx.x];
    d_start[u] = st;
    d_cursor[u] = st;
    if (d_need[u]) {
        int li = atomicAdd(&d_nneed, 1);
        d_list[li] = u;
    }
}

// ---------------- K6: CSR build (int4) --------------------------------------
__global__ void k_csr(const int* __restrict__ row, const int* __restrict__ col,
                      const int* __restrict__ x) {
    int i4 = blockIdx.x * blockDim.x + threadIdx.x;
    if (i4 >= N_EDGES / 4) return;
    int4 c = ((const int4*)col)[i4];
    int4 r = ((const int4*)row)[i4];
#define DO_E(rr, cc) \
    if (d_need[cc]) { \
        int idx = atomicAdd(&d_cursor[cc], 1); \
        float w = d_dinv[rr] * d_dinv[cc]; \
        d_csr[idx] = make_int2(x[rr], __float_as_int(w)); \
    }
    DO_E(r.x, c.x) DO_E(r.y, c.y) DO_E(r.z, c.z) DO_E(r.w, c.w)
#undef DO_E
}

// ---------------- K7: fused gather: h1 + relu + layer-2 reduction -----------
__global__ void k_gather(const float* __restrict__ b1, const int* __restrict__ x) {
    __shared__ float ssv[H2];
    int tid = threadIdx.x;
    ssv[tid] = 0.f;
    __syncthreads();
    int lane = tid & 31;
    int gw = (blockIdx.x * blockDim.x + tid) >> 5;
    int nw = (gridDim.x * blockDim.x) >> 5;
    int nn = d_nneed;
    float4 bb0 = ((const float4*)b1)[lane];
    float4 bb1 = ((const float4*)b1)[lane + 32];
    const float4* EW4 = (const float4*)d_EW;
    float4 sv0 = make_float4(0, 0, 0, 0), sv1 = make_float4(0, 0, 0, 0);
    for (int idx = gw; idx < nn; idx += nw) {
        int u = d_list[idx];
        float du = d_dinv[u];
        float d2 = du * du;
        const float4* su = EW4 + (size_t)x[u] * 64;
        float4 a0 = su[lane], a1 = su[lane + 32];
        a0.x *= d2; a0.y *= d2; a0.z *= d2; a0.w *= d2;
        a1.x *= d2; a1.y *= d2; a1.z *= d2; a1.w *= d2;
        int s0 = d_start[u], len = d_deg[u];
        for (int b = 0; b < len; b += 32) {
            int i = b + lane;
            int2 ev = (i < len) ? d_csr[s0 + i] : make_int2(0, 0);
            int n = min(32, len - b);
            for (int j = 0; j < n; j++) {
                int xr = __shfl_sync(0xffffffffu, ev.x, j);
                float w = __int_as_float(__shfl_sync(0xffffffffu, ev.y, j));
                const float4* p = EW4 + (size_t)xr * 64;
                float4 v0 = p[lane], v1 = p[lane + 32];
                a0.x += w * v0.x; a0.y += w * v0.y; a0.z += w * v0.z; a0.w += w * v0.w;
                a1.x += w * v1.x; a1.y += w * v1.y; a1.z += w * v1.z; a1.w += w * v1.w;
            }
        }
        float ct = d_coef[u] + (float)d_cnt[u] * d2;
        sv0.x += ct * fmaxf(a0.x + bb0.x, 0.f);
        sv0.y += ct * fmaxf(a0.y + bb0.y, 0.f);
        sv0.z += ct * fmaxf(a0.z + bb0.z, 0.f);
        sv0.w += ct * fmaxf(a0.w + bb0.w, 0.f);
        sv1.x += ct * fmaxf(a1.x + bb1.x, 0.f);
        sv1.y += ct * fmaxf(a1.y + bb1.y, 0.f);
        sv1.z += ct * fmaxf(a1.z + bb1.z, 0.f);
        sv1.w += ct * fmaxf(a1.w + bb1.w, 0.f);
    }
    atomicAdd(&ssv[4 * lane + 0], sv0.x);
    atomicAdd(&ssv[4 * lane + 1], sv0.y);
    atomicAdd(&ssv[4 * lane + 2], sv0.z);
    atomicAdd(&ssv[4 * lane + 3], sv0.w);
    atomicAdd(&ssv[128 + 4 * lane + 0], sv1.x);
    atomicAdd(&ssv[128 + 4 * lane + 1], sv1.y);
    atomicAdd(&ssv[128 + 4 * lane + 2], sv1.z);
    atomicAdd(&ssv[128 + 4 * lane + 3], sv1.w);
    __syncthreads();
    if (tid < 64) {
        float4 p = ((float4*)ssv)[tid];
        red4(((float4*)d_svec) + tid, p.x, p.y, p.z, p.w);
    }
}

// ---------------- K8: zbar = (svec/1024) @ W2 + b2 --------------------------
__global__ void k_zbar(const float* __restrict__ W2, const float* __restrict__ b2) {
    int j = threadIdx.x;  // 128
    float acc = 0.f;
    for (int k = 0; k < H2; k++) acc += d_svec[k] * W2[k * HID + j];
    d_zbar[j] = acc * (1.0f / (float)N_POS) + b2[j];
}

// ---------------- K9: out = zbar @ Wc + bc ----------------------------------
__global__ void k_out(const float* __restrict__ Wc, const float* __restrict__ bc,
                      float* __restrict__ out) {
    __shared__ float zb[HID];
    if (threadIdx.x < HID) zb[threadIdx.x] = d_zbar[threadIdx.x];
    __syncthreads();
    int c = blockIdx.x * 256 + threadIdx.x;
    float acc = bc[c];
#pragma unroll 8
    for (int j = 0; j < HID; j++) acc += zb[j] * Wc[j * VOCABSZ + c];
    out[c] = acc;
}

extern "C" void kernel_launch(void* const* d_in, const int* in_sizes, int n_in,
                              void* d_out, int out_size) {
    const int*   x    = (const int*)d_in[0];
    const int*   ei   = (const int*)d_in[1];
    const int*   pos  = (const int*)d_in[2];
    const float* emb  = (const float*)d_in[3];
    const float* W1   = (const float*)d_in[4];
    const float* b1   = (const float*)d_in[5];
    const float* W2   = (const float*)d_in[6];
    const float* b2   = (const float*)d_in[7];
    const float* Wc   = (const float*)d_in[8];
    const float* bc   = (const float*)d_in[9];
    float* out = (float*)d_out;
    const int* row = ei;
    const int* col = ei + N_EDGES;

    void *pdeg, *pcnt, *pneed, *pcoef, *psvec, *pnn;
    cudaGetSymbolAddress(&pdeg, d_deg);
    cudaGetSymbolAddress(&pcnt, d_cnt);
    cudaGetSymbolAddress(&pneed, d_need);
    cudaGetSymbolAddress(&pcoef, d_coef);
    cudaGetSymbolAddress(&psvec, d_svec);
    cudaGetSymbolAddress(&pnn, d_nneed);
    cudaMemsetAsync(pdeg, 0, N_NODES * sizeof(int), 0);
    cudaMemsetAsync(pcnt, 0, N_NODES * sizeof(int), 0);
    cudaMemsetAsync(pneed, 0, N_NODES, 0);
    cudaMemsetAsync(pcoef, 0, N_NODES * sizeof(float), 0);
    cudaMemsetAsync(psvec, 0, H2 * sizeof(float), 0);
    cudaMemsetAsync(pnn, 0, sizeof(int), 0);

    k_ew<<<VOCABSZ / 16, 256>>>(emb, W1);
    k_deg<<<(N_EDGES / 4 + 255) / 256, 256>>>(col, pos);
    k_dinv<<<(N_NODES + 255) / 256, 256>>>(pos);
    k_coef<<<(N_EDGES / 4 + 255) / 256, 256>>>(row, col);
    k_scan1<<<NSCAN_BLK, 256>>>();
    k_scan2<<<1, 256>>>();
    k_scan3<<<NSCAN_BLK, 256>>>();
    k_csr<<<(N_EDGES / 4 + 255) / 256, 256>>>(row, col, x);
    k_gather<<<1024, 256>>>(b1, x);
    k_zbar<<<1, 128>>>(W2, b2);
    k_out<<<VOCABSZ / 256, 256>>>(Wc, bc, out);
}